// round 15
// baseline (speedup 1.0000x reference)
#include <cuda_runtime.h>
#include <cuda_fp16.h>
#include <math.h>
#include <cstdint>

#define EPSF 1e-5f

// Problem constants
#define Bn 4
#define Cn 128
#define Gn 64
#define SCn 512
#define Hh 256
#define Hl 128

#define HFTOT ((size_t)Bn * Cn * Hh * Hh)   // 33554432
#define LFTOT ((size_t)Bn * Cn * Hl * Hl)   // 8388608

// padded half2 activation tensors: [b][pair(64)][H+2][W2]
#define W2H 260
#define W2L 132
#define HFP2 ((size_t)Bn * 64 * (Hh + 2) * W2H)
#define LFP2 ((size_t)Bn * 64 * (Hl + 2) * W2L)

#define WTSZ (8 * 9 * 128 * 8)

// ---------------------------------------------------------------------------
// Device scratch (no cudaMalloc allowed)
// ---------------------------------------------------------------------------
__device__ __align__(128) __half2 g_y2p[HFP2 + LFP2];
__device__ __align__(128) __half2 g_cout[(HFTOT + LFTOT) / 2];
__device__ __align__(128) __half2 g_wTh[2 * WTSZ];
__device__ float g_wsp[2][Bn * 256 * 9];
__device__ float g_weff[2][Bn * Cn * 2 * 9];
__device__ float g_gbias[2][Bn * Cn];
__device__ float g_m1[2][Bn * Cn];
__device__ float g_rs1[2][Bn * Cn];
__device__ float g_sum[2 * Bn * Cn];
__device__ float g_ssq[2 * Bn * Cn];

// ---------------------------------------------------------------------------
// prep: zero stat accumulators + transform dense weights (both branches).
// A-layout XOR-swizzle: kp ^= (oc & 4) to make A-fragment LDS conflict-free.
// ---------------------------------------------------------------------------
__global__ void k_prep(const float* __restrict__ cw_h, const float* __restrict__ cw_l) {
    int idx = blockIdx.x * blockDim.x + threadIdx.x;
    if (idx < 2 * Bn * Cn) { g_sum[idx] = 0.f; g_ssq[idx] = 0.f; }
    if (idx >= 2 * Cn * 64 * 9) return;
    int br = idx >= Cn * 64 * 9;
    int l = br ? idx - Cn * 64 * 9 : idx;
    const float* cw = br ? cw_l : cw_h;
    int oc = l / (64 * 9);
    int rem = l % (64 * 9);
    int p = rem / 9, tap = rem % 9;
    int cc = p >> 3, kp = p & 7;
    float w0 = cw[((size_t)oc * Cn + 2 * p) * 9 + tap];
    float w1 = cw[((size_t)oc * Cn + 2 * p + 1) * 9 + tap];
    int kps = kp ^ (oc & 4);   // bank-conflict swizzle
    g_wTh[(size_t)br * WTSZ + (((size_t)cc * 9 + tap) * Cn + oc) * 8 + kps] =
        __floats2half2_rn(w0, w1);
}

// ---------------------------------------------------------------------------
__global__ void k_wsp(const float* __restrict__ s, const float* __restrict__ spw,
                      const float* __restrict__ spb, int br) {
    int b = blockIdx.x >> 8;
    int oc = blockIdx.x & 255;
    int t = threadIdx.x;
    const int R[5] = {1, 0, 1, 2, 1};

    float acc[9];
#pragma unroll
    for (int i = 0; i < 9; i++) acc[i] = 0.f;

    for (int c = t; c < SCn; c += 128) {
        float sv[9], wv[9];
        const float* sp = s + (size_t)(b * SCn + c) * 9;
        const float* wp = spw + (size_t)(oc * SCn + c) * 9;
#pragma unroll
        for (int i = 0; i < 9; i++) { sv[i] = sp[i]; wv[i] = wp[i]; }
#pragma unroll
        for (int oy = 0; oy < 3; oy++)
#pragma unroll
            for (int ox = 0; ox < 3; ox++) {
                float a = 0.f;
#pragma unroll
                for (int ky = 0; ky < 3; ky++)
#pragma unroll
                    for (int kx = 0; kx < 3; kx++)
                        a += sv[R[oy + ky] * 3 + R[ox + kx]] * wv[ky * 3 + kx];
                acc[oy * 3 + ox] += a;
            }
    }

    __shared__ float red[9][128];
#pragma unroll
    for (int i = 0; i < 9; i++) red[i][t] = acc[i];
    __syncthreads();
    for (int off = 64; off; off >>= 1) {
        if (t < off)
#pragma unroll
            for (int i = 0; i < 9; i++) red[i][t] += red[i][t + off];
        __syncthreads();
    }
    if (t < 9) g_wsp[br][(size_t)(b * 256 + oc) * 9 + t] = red[t][0] + spb[oc];
}

// ---------------------------------------------------------------------------
// Pointwise/bias predictor (style mean computed inline) + weight fusion.
// ---------------------------------------------------------------------------
__global__ void k_weff(const float* __restrict__ s,
                       const float* __restrict__ pww, const float* __restrict__ pwb,
                       const float* __restrict__ bw, const float* __restrict__ bb, int br) {
    int b = blockIdx.x >> 7;
    int o = blockIdx.x & 127;
    int t = threadIdx.x;

    float a0 = 0.f, a1 = 0.f, ab = 0.f;
    for (int c = t; c < SCn; c += 128) {
        const float* sp = s + (size_t)(b * SCn + c) * 9;
        float sv = 0.f;
#pragma unroll
        for (int i = 0; i < 9; i++) sv += sp[i];
        sv *= (1.f / 9.f);
        a0 += sv * pww[(size_t)(o * 2 + 0) * SCn + c];
        a1 += sv * pww[(size_t)(o * 2 + 1) * SCn + c];
        ab += sv * bw[(size_t)o * SCn + c];
    }
    __shared__ float r0[128], r1[128], r2[128];
    r0[t] = a0; r1[t] = a1; r2[t] = ab;
    __syncthreads();
    for (int off = 64; off; off >>= 1) {
        if (t < off) { r0[t] += r0[t + off]; r1[t] += r1[t + off]; r2[t] += r2[t + off]; }
        __syncthreads();
    }
    __shared__ float w0s, w1s;
    if (t == 0) {
        w0s = r0[0] + pwb[o * 2 + 0];
        w1s = r1[0] + pwb[o * 2 + 1];
        g_gbias[br][b * Cn + o] = r2[0] + bb[o];
    }
    __syncthreads();
    if (t < 18) {
        int j = t / 9, k = t % 9;
        int g = o >> 1;
        float w = w0s * g_wsp[br][(size_t)(b * 256 + (g * 2 + 0) * 2 + j) * 9 + k]
                + w1s * g_wsp[br][(size_t)(b * 256 + (g * 2 + 1) * 2 + j) * 9 + k];
        g_weff[br][(size_t)((b * Cn + o) * 2 + j) * 9 + k] = w;
    }
}

// ---------------------------------------------------------------------------
__global__ void k_istats(const float* __restrict__ x, int H, int br) {
    int bc = blockIdx.x;
    int HW = H * H;
    const float4* p4 = (const float4*)(x + (size_t)bc * HW);
    int n4 = HW >> 2;
    float s = 0.f, ss = 0.f;
    for (int i = threadIdx.x; i < n4; i += 256) {
        float4 v = p4[i];
        s += v.x + v.y + v.z + v.w;
        ss += v.x * v.x + v.y * v.y + v.z * v.z + v.w * v.w;
    }
    __shared__ float rs[256], rss[256];
    rs[threadIdx.x] = s; rss[threadIdx.x] = ss;
    __syncthreads();
    for (int off = 128; off; off >>= 1) {
        if (threadIdx.x < off) { rs[threadIdx.x] += rs[threadIdx.x + off]; rss[threadIdx.x] += rss[threadIdx.x + off]; }
        __syncthreads();
    }
    if (threadIdx.x == 0) {
        float m = rs[0] / HW;
        float var = rss[0] / HW - m * m;
        g_m1[br][bc] = m;
        g_rs1[br][bc] = rsqrtf(var + EPSF);
    }
}

// ---------------------------------------------------------------------------
// Fused grouped conv (inorm1 inline), reflect pad, writes padded half2
// interior AND the reflect halo (boundary tiles own all reflected cells).
// ---------------------------------------------------------------------------
__global__ void k_gconv(const float* __restrict__ xin, int H, int W2p, size_t off2, int br) {
    int bg = blockIdx.y;
    int b = bg >> 6, g = bg & 63;
    int tiles = H >> 5;
    int ty0 = (blockIdx.x / tiles) << 5;
    int tx0 = (blockIdx.x % tiles) << 5;
    int t = threadIdx.x;

    __shared__ float tile[2][34][34];
    __shared__ float w[2][2][9];
    __shared__ float bsh[2];

    if (t < 36) {
        int oc = t / 18, j = (t / 9) & 1, k = t % 9;
        w[oc][j][k] = g_weff[br][(size_t)((b * Cn + g * 2 + oc) * 2 + j) * 9 + k];
    }
    if (t < 2) bsh[t] = g_gbias[br][b * Cn + g * 2 + t];

#pragma unroll
    for (int ic = 0; ic < 2; ic++) {
        int ch = g * 2 + ic;
        float m = g_m1[br][b * Cn + ch], rs = g_rs1[br][b * Cn + ch];
        const float* xp = xin + (size_t)(b * Cn + ch) * H * H;
        for (int i = t; i < 34 * 34; i += 256) {
            int ly = i / 34, lx = i % 34;
            int gy = ty0 - 1 + ly, gx = tx0 - 1 + lx;
            gy = gy < 0 ? -gy : (gy >= H ? 2 * H - 2 - gy : gy);
            gx = gx < 0 ? -gx : (gx >= H ? 2 * H - 2 - gx : gx);
            tile[ic][ly][lx] = (xp[(size_t)gy * H + gx] - m) * rs;
        }
    }
    __syncthreads();

    __half2* dst = g_y2p + off2 + (size_t)(b * 64 + g) * (H + 2) * W2p;
    for (int p = t; p < 1024; p += 256) {
        int y = p >> 5, x = p & 31;
        float a0 = bsh[0], a1 = bsh[1];
#pragma unroll
        for (int ic = 0; ic < 2; ic++)
#pragma unroll
            for (int ky = 0; ky < 3; ky++)
#pragma unroll
                for (int kx = 0; kx < 3; kx++) {
                    float v = tile[ic][y + ky][x + kx];
                    a0 += v * w[0][ic][ky * 3 + kx];
                    a1 += v * w[1][ic][ky * 3 + kx];
                }
        __half2 h2 = __floats2half2_rn(a0, a1);
        int gy = ty0 + y, gx = tx0 + x;
        size_t rowi = (size_t)(1 + gy) * W2p;
        dst[rowi + 1 + gx] = h2;
        // reflect halo (padded row0 = orig row1, col0 = orig col1, etc.)
        if (gx == 1)     dst[rowi] = h2;
        if (gx == H - 2) dst[rowi + H + 1] = h2;
        if (gy == 1) {
            dst[1 + gx] = h2;
            if (gx == 1)     dst[0] = h2;
            if (gx == H - 2) dst[H + 1] = h2;
        }
        if (gy == H - 2) {
            size_t rb = (size_t)(H + 1) * W2p;
            dst[rb + 1 + gx] = h2;
            if (gx == 1)     dst[rb] = h2;
            if (gx == H - 2) dst[rb + H + 1] = h2;
        }
    }
}

// ===========================================================================
// Dense 3x3 conv via mma.sync m16n8k16 fp16 (tap-loop implicit GEMM).
// Single-sync double-buffer pipeline; A-LDS conflict-free via XOR swizzle.
// ===========================================================================
#define AW_BYTES 36864
#define IT_BYTES 6912
#define SMEM_MMA (2 * AW_BYTES + 2 * IT_BYTES)   // 87552

__device__ __forceinline__ uint32_t s2u(const void* p) {
    uint32_t a;
    asm("{ .reg .u64 t; cvta.to.shared.u64 t, %1; cvt.u32.u64 %0, t; }" : "=r"(a) : "l"(p));
    return a;
}

#define MMAH(d, A, b0, b1)                                               \
    asm volatile("mma.sync.aligned.m16n8k16.row.col.f32.f16.f16.f32 "    \
                 "{%0,%1,%2,%3}, {%4,%5,%6,%7}, {%8,%9}, {%0,%1,%2,%3};" \
                 : "+f"(d[0]), "+f"(d[1]), "+f"(d[2]), "+f"(d[3])        \
                 : "r"(A[0]), "r"(A[1]), "r"(A[2]), "r"(A[3]),           \
                   "r"(b0), "r"(b1))

__global__ void __launch_bounds__(256) k_dconv_mma(
    const float* __restrict__ cb, const __half2* __restrict__ wT,
    int H, int W2p, size_t inoff2, size_t coutoff2, int statoff) {

    extern __shared__ __align__(16) char smem[];
    const int t = threadIdx.x;
    const int wid = t >> 5, lane = t & 31;
    const int gid = lane >> 2, tig = lane & 3;
    const int s4 = gid & 4;                 // A swizzle key (matches k_prep)
    const int moff = (wid & 3) * 32, noff = (wid >> 2) * 64;
    const int px0 = blockIdx.x * 32, py0 = blockIdx.y * 4;
    const int b = blockIdx.z;
    const int HW = H * H;
    uint32_t sb = s2u(smem);

    const __half2* inb2 = g_y2p + inoff2 + (size_t)b * 64 * (H + 2) * W2p;

    int bidx[8];
#pragma unroll
    for (int j = 0; j < 8; j++) {
        int n = noff + j * 8 + gid;
        bidx[j] = (n >> 5) * 36 + (n & 31);
    }

    float acc[2][8][4];
#pragma unroll
    for (int m = 0; m < 2; m++)
#pragma unroll
        for (int j = 0; j < 8; j++)
#pragma unroll
            for (int q = 0; q < 4; q++) acc[m][j][q] = 0.f;

    auto issue = [&](int cc) {
        int s = cc & 1;
        const __half2* srcw = wT + (size_t)cc * 9216;
        uint32_t dstw = sb + s * AW_BYTES;
        for (int u = t; u < 2304; u += 256)
            asm volatile("cp.async.cg.shared.global [%0], [%1], 16;" ::
                         "r"(dstw + u * 16), "l"(srcw + u * 4));
        uint32_t dsti = sb + 2 * AW_BYTES + s * IT_BYTES;
        for (int v = t; v < 432; v += 256) {
            int kp = v / 54, rem = v % 54;
            int ry = rem / 9, q = rem % 9;
            const __half2* g = inb2 +
                ((size_t)(cc * 8 + kp) * (H + 2) + (py0 + ry)) * W2p + px0 + q * 4;
            asm volatile("cp.async.cg.shared.global [%0], [%1], 16;" ::
                         "r"(dsti + (uint32_t)((kp * 216 + ry * 36 + q * 4) * 4)), "l"(g));
        }
        asm volatile("cp.async.commit_group;" ::: "memory");
    };

    issue(0);
    for (int cc = 0; cc < 8; cc++) {
        asm volatile("cp.async.wait_group 0;" ::: "memory");
        __syncthreads();
        if (cc < 7) issue(cc + 1);

        const uint32_t* Aw = (const uint32_t*)(smem + (cc & 1) * AW_BYTES);
        const uint32_t* IT = (const uint32_t*)(smem + 2 * AW_BYTES + (cc & 1) * IT_BYTES);

#pragma unroll
        for (int tap = 0; tap < 9; tap++) {
            uint32_t a[2][4];
#pragma unroll
            for (int m = 0; m < 2; m++) {
                int base = tap * 1024 + (moff + m * 16 + gid) * 8;
                a[m][0] = Aw[base + (tig ^ s4)];
                a[m][1] = Aw[base + 64 + (tig ^ s4)];
                a[m][2] = Aw[base + ((tig + 4) ^ s4)];
                a[m][3] = Aw[base + 64 + ((tig + 4) ^ s4)];
            }
            int toff = tig * 216 + (tap / 3) * 36 + (tap % 3);
#pragma unroll
            for (int j = 0; j < 8; j++) {
                uint32_t b0 = IT[toff + bidx[j]];
                uint32_t b1 = IT[toff + 864 + bidx[j]];
                MMAH(acc[0][j], a[0], b0, b1);
                MMAH(acc[1][j], a[1], b0, b1);
            }
        }
    }

    // ---- epilogue: bias + half2 store to scratch + stats ----
#pragma unroll
    for (int m = 0; m < 2; m++) {
        int ocm = moff + m * 16 + gid;
        float bv0 = cb[ocm], bv1 = cb[ocm + 8];
        float s0 = 0.f, q0 = 0.f, s1 = 0.f, q1 = 0.f;
        __half2* o0 = g_cout + coutoff2 + (((size_t)(b * Cn + ocm) * HW) >> 1);
        __half2* o1 = g_cout + coutoff2 + (((size_t)(b * Cn + ocm + 8) * HW) >> 1);
#pragma unroll
        for (int j = 0; j < 8; j++) {
            int n = noff + j * 8 + tig * 2;
            int pr = py0 + (n >> 5), pc = px0 + (n & 31);
            float v00 = acc[m][j][0] + bv0, v01 = acc[m][j][1] + bv0;
            float v10 = acc[m][j][2] + bv1, v11 = acc[m][j][3] + bv1;
            size_t pp = ((size_t)pr * H + pc) >> 1;
            o0[pp] = __floats2half2_rn(v00, v01);
            o1[pp] = __floats2half2_rn(v10, v11);
            s0 += v00 + v01; q0 += v00 * v00 + v01 * v01;
            s1 += v10 + v11; q1 += v10 * v10 + v11 * v11;
        }
#pragma unroll
        for (int o = 1; o <= 2; o <<= 1) {
            s0 += __shfl_xor_sync(0xffffffffu, s0, o);
            q0 += __shfl_xor_sync(0xffffffffu, q0, o);
            s1 += __shfl_xor_sync(0xffffffffu, s1, o);
            q1 += __shfl_xor_sync(0xffffffffu, q1, o);
        }
        if (tig == 0) {
            atomicAdd(&g_sum[statoff + b * Cn + ocm], s0);
            atomicAdd(&g_ssq[statoff + b * Cn + ocm], q0);
            atomicAdd(&g_sum[statoff + b * Cn + ocm + 8], s1);
            atomicAdd(&g_ssq[statoff + b * Cn + ocm + 8], q1);
        }
    }
}

// ---------------------------------------------------------------------------
// Final: read half2 conv scratch, instance norm + leaky ReLU, write fp32 out.
// ---------------------------------------------------------------------------
__global__ void k_final(float* __restrict__ out) {
    size_t totalp = (HFTOT + LFTOT) >> 1;
    for (size_t idx = (size_t)blockIdx.x * blockDim.x + threadIdx.x; idx < totalp;
         idx += (size_t)gridDim.x * blockDim.x) {
        size_t e = idx << 1;
        int stat; float inv;
        if (e < HFTOT) {
            stat = (int)(e >> 16);
            inv = 1.f / 65536.f;
        } else {
            stat = Bn * Cn + (int)((e - HFTOT) >> 14);
            inv = 1.f / 16384.f;
        }
        float m = g_sum[stat] * inv;
        float var = g_ssq[stat] * inv - m * m;
        float rs = rsqrtf(var + EPSF);
        float2 v = __half22float2(g_cout[idx]);
        float a = (v.x - m) * rs;
        float c = (v.y - m) * rs;
        a = a >= 0.f ? a : 0.2f * a;
        c = c >= 0.f ? c : 0.2f * c;
        reinterpret_cast<float2*>(out)[idx] = make_float2(a, c);
    }
}

// ---------------------------------------------------------------------------
extern "C" void kernel_launch(void* const* d_in, const int* in_sizes, int n_in,
                              void* d_out, int out_size) {
    const float* c_hf = (const float*)d_in[0];
    const float* c_lf = (const float*)d_in[1];
    const float* s_hf = (const float*)d_in[2];
    const float* s_lf = (const float*)d_in[3];
    const float* kp_h_sp_w = (const float*)d_in[4];
    const float* kp_h_sp_b = (const float*)d_in[5];
    const float* kp_h_pw_w = (const float*)d_in[6];
    const float* kp_h_pw_b = (const float*)d_in[7];
    const float* kp_h_b_w  = (const float*)d_in[8];
    const float* kp_h_b_b  = (const float*)d_in[9];
    const float* kp_l_sp_w = (const float*)d_in[10];
    const float* kp_l_sp_b = (const float*)d_in[11];
    const float* kp_l_pw_w = (const float*)d_in[12];
    const float* kp_l_pw_b = (const float*)d_in[13];
    const float* kp_l_b_w  = (const float*)d_in[14];
    const float* kp_l_b_b  = (const float*)d_in[15];
    const float* conv_h_w  = (const float*)d_in[16];
    const float* conv_h_b  = (const float*)d_in[17];
    const float* conv_l_w  = (const float*)d_in[18];
    const float* conv_l_b  = (const float*)d_in[19];
    float* out = (float*)d_out;

    cudaFuncSetAttribute(k_dconv_mma, cudaFuncAttributeMaxDynamicSharedMemorySize, SMEM_MMA);

    __half2* wTh; cudaGetSymbolAddress((void**)&wTh, g_wTh);
    __half2* wTl = wTh + WTSZ;

    // Streams: s1 = hf chain, s2 = lf chain, s3 = istats (input-only dep).
    cudaStream_t s1, s2, s3;
    cudaStreamCreateWithFlags(&s1, cudaStreamNonBlocking);
    cudaStreamCreateWithFlags(&s2, cudaStreamNonBlocking);
    cudaStreamCreateWithFlags(&s3, cudaStreamNonBlocking);
    cudaEvent_t e0, ep, eish, eisl, e1, e2;
    cudaEventCreateWithFlags(&e0, cudaEventDisableTiming);
    cudaEventCreateWithFlags(&ep, cudaEventDisableTiming);
    cudaEventCreateWithFlags(&eish, cudaEventDisableTiming);
    cudaEventCreateWithFlags(&eisl, cudaEventDisableTiming);
    cudaEventCreateWithFlags(&e1, cudaEventDisableTiming);
    cudaEventCreateWithFlags(&e2, cudaEventDisableTiming);

    // Fork all side streams from the capture stream origin.
    cudaEventRecord(e0, 0);
    cudaStreamWaitEvent(s1, e0, 0);
    cudaStreamWaitEvent(s2, e0, 0);
    cudaStreamWaitEvent(s3, e0, 0);

    // prep on main stream (needed by dconv + final only)
    k_prep<<<(2 * Cn * 64 * 9 + 255) / 256, 256>>>(conv_h_w, conv_l_w);
    cudaEventRecord(ep, 0);

    // istats on s3 (depends only on raw inputs)
    k_istats<<<Bn * Cn, 256, 0, s3>>>(c_hf, Hh, 0);
    cudaEventRecord(eish, s3);
    k_istats<<<Bn * Cn, 256, 0, s3>>>(c_lf, Hl, 1);
    cudaEventRecord(eisl, s3);

    // ---- HF branch on s1 ----
    k_wsp<<<Bn * 256, 128, 0, s1>>>(s_hf, kp_h_sp_w, kp_h_sp_b, 0);
    k_weff<<<Bn * Cn, 128, 0, s1>>>(s_hf, kp_h_pw_w, kp_h_pw_b, kp_h_b_w, kp_h_b_b, 0);
    cudaStreamWaitEvent(s1, eish, 0);
    k_gconv<<<dim3(64, Bn * Gn), 256, 0, s1>>>(c_hf, Hh, W2H, 0, 0);
    cudaStreamWaitEvent(s1, ep, 0);
    k_dconv_mma<<<dim3(Hh / 32, Hh / 4, Bn), 256, SMEM_MMA, s1>>>(
        conv_h_b, wTh, Hh, W2H, 0, 0, 0);
    cudaEventRecord(e1, s1);

    // ---- LF branch on s2 ----
    k_wsp<<<Bn * 256, 128, 0, s2>>>(s_lf, kp_l_sp_w, kp_l_sp_b, 1);
    k_weff<<<Bn * Cn, 128, 0, s2>>>(s_lf, kp_l_pw_w, kp_l_pw_b, kp_l_b_w, kp_l_b_b, 1);
    cudaStreamWaitEvent(s2, eisl, 0);
    k_gconv<<<dim3(16, Bn * Gn), 256, 0, s2>>>(c_lf, Hl, W2L, HFP2, 1);
    cudaStreamWaitEvent(s2, ep, 0);
    k_dconv_mma<<<dim3(Hl / 32, Hl / 4, Bn), 256, SMEM_MMA, s2>>>(
        conv_l_b, wTl, Hl, W2L, HFP2, HFTOT / 2, Bn * Cn);
    cudaEventRecord(e2, s2);

    // ---- join, then final norm + lrelu on the main stream ----
    cudaStreamWaitEvent(0, e1, 0);
    cudaStreamWaitEvent(0, e2, 0);
    k_final<<<16384, 256>>>(out);

    cudaEventDestroy(e0);
    cudaEventDestroy(ep);
    cudaEventDestroy(eish);
    cudaEventDestroy(eisl);
    cudaEventDestroy(e1);
    cudaEventDestroy(e2);
    cudaStreamDestroy(s1);
    cudaStreamDestroy(s2);
    cudaStreamDestroy(s3);
}

// round 17
// speedup vs baseline: 1.0136x; 1.0136x over previous
#include <cuda_runtime.h>
#include <cuda_fp16.h>
#include <math.h>
#include <cstdint>

#define EPSF 1e-5f

// Problem constants
#define Bn 4
#define Cn 128
#define Gn 64
#define SCn 512
#define Hh 256
#define Hl 128

#define HFTOT ((size_t)Bn * Cn * Hh * Hh)   // 33554432
#define LFTOT ((size_t)Bn * Cn * Hl * Hl)   // 8388608

// padded half2 activation tensors: [b][pair(64)][H+2][W2]
#define W2H 260
#define W2L 132
#define HFP2 ((size_t)Bn * 64 * (Hh + 2) * W2H)
#define LFP2 ((size_t)Bn * 64 * (Hl + 2) * W2L)

#define WTSZ (8 * 9 * 128 * 8)

// ---------------------------------------------------------------------------
// Device scratch (no cudaMalloc allowed)
// ---------------------------------------------------------------------------
__device__ __align__(128) __half2 g_y2p[HFP2 + LFP2];
__device__ __align__(128) __half2 g_cout[(HFTOT + LFTOT) / 2];
__device__ __align__(128) __half2 g_wTh[2 * WTSZ];
__device__ float g_wsp[2][Bn * 256 * 9];
__device__ float g_weff[2][Bn * Cn * 2 * 9];
__device__ float g_gbias[2][Bn * Cn];
__device__ float g_m1[2][Bn * Cn];
__device__ float g_rs1[2][Bn * Cn];
__device__ float g_sum[2 * Bn * Cn];
__device__ float g_ssq[2 * Bn * Cn];

// ---------------------------------------------------------------------------
// prep: zero stat accumulators + transform dense weights (both branches).
// FRAGMENT-MAJOR A layout: word index
//   ((cc*9 + tap)*8 + m16tile)*128 + lane*4 + q
// where lane = gid*4 + tig, q = (row-half) + 2*(kp-half). This makes each
// thread's 4 A-fragment words contiguous -> one LDS.128 per m-tile per tap.
// ---------------------------------------------------------------------------
__global__ void k_prep(const float* __restrict__ cw_h, const float* __restrict__ cw_l) {
    int idx = blockIdx.x * blockDim.x + threadIdx.x;
    if (idx < 2 * Bn * Cn) { g_sum[idx] = 0.f; g_ssq[idx] = 0.f; }
    if (idx >= 2 * Cn * 64 * 9) return;
    int br = idx >= Cn * 64 * 9;
    int l = br ? idx - Cn * 64 * 9 : idx;
    const float* cw = br ? cw_l : cw_h;
    int oc = l / (64 * 9);
    int rem = l % (64 * 9);
    int p = rem / 9, tap = rem % 9;
    int cc = p >> 3, kp = p & 7;
    float w0 = cw[((size_t)oc * Cn + 2 * p) * 9 + tap];
    float w1 = cw[((size_t)oc * Cn + 2 * p + 1) * 9 + tap];
    int mt = oc >> 4;
    int r = oc & 15;
    int gid = r & 7, half = r >> 3;
    int tig = kp & 3, hi = kp >> 2;
    int q = half + 2 * hi;
    size_t w = (((size_t)cc * 9 + tap) * 8 + mt) * 128 + (gid * 4 + tig) * 4 + q;
    g_wTh[(size_t)br * WTSZ + w] = __floats2half2_rn(w0, w1);
}

// ---------------------------------------------------------------------------
__global__ void k_wsp(const float* __restrict__ s, const float* __restrict__ spw,
                      const float* __restrict__ spb, int br) {
    int b = blockIdx.x >> 8;
    int oc = blockIdx.x & 255;
    int t = threadIdx.x;
    const int R[5] = {1, 0, 1, 2, 1};

    float acc[9];
#pragma unroll
    for (int i = 0; i < 9; i++) acc[i] = 0.f;

    for (int c = t; c < SCn; c += 128) {
        float sv[9], wv[9];
        const float* sp = s + (size_t)(b * SCn + c) * 9;
        const float* wp = spw + (size_t)(oc * SCn + c) * 9;
#pragma unroll
        for (int i = 0; i < 9; i++) { sv[i] = sp[i]; wv[i] = wp[i]; }
#pragma unroll
        for (int oy = 0; oy < 3; oy++)
#pragma unroll
            for (int ox = 0; ox < 3; ox++) {
                float a = 0.f;
#pragma unroll
                for (int ky = 0; ky < 3; ky++)
#pragma unroll
                    for (int kx = 0; kx < 3; kx++)
                        a += sv[R[oy + ky] * 3 + R[ox + kx]] * wv[ky * 3 + kx];
                acc[oy * 3 + ox] += a;
            }
    }

    __shared__ float red[9][128];
#pragma unroll
    for (int i = 0; i < 9; i++) red[i][t] = acc[i];
    __syncthreads();
    for (int off = 64; off; off >>= 1) {
        if (t < off)
#pragma unroll
            for (int i = 0; i < 9; i++) red[i][t] += red[i][t + off];
        __syncthreads();
    }
    if (t < 9) g_wsp[br][(size_t)(b * 256 + oc) * 9 + t] = red[t][0] + spb[oc];
}

// ---------------------------------------------------------------------------
// Pointwise/bias predictor (style mean computed inline) + weight fusion.
// ---------------------------------------------------------------------------
__global__ void k_weff(const float* __restrict__ s,
                       const float* __restrict__ pww, const float* __restrict__ pwb,
                       const float* __restrict__ bw, const float* __restrict__ bb, int br) {
    int b = blockIdx.x >> 7;
    int o = blockIdx.x & 127;
    int t = threadIdx.x;

    float a0 = 0.f, a1 = 0.f, ab = 0.f;
    for (int c = t; c < SCn; c += 128) {
        const float* sp = s + (size_t)(b * SCn + c) * 9;
        float sv = 0.f;
#pragma unroll
        for (int i = 0; i < 9; i++) sv += sp[i];
        sv *= (1.f / 9.f);
        a0 += sv * pww[(size_t)(o * 2 + 0) * SCn + c];
        a1 += sv * pww[(size_t)(o * 2 + 1) * SCn + c];
        ab += sv * bw[(size_t)o * SCn + c];
    }
    __shared__ float r0[128], r1[128], r2[128];
    r0[t] = a0; r1[t] = a1; r2[t] = ab;
    __syncthreads();
    for (int off = 64; off; off >>= 1) {
        if (t < off) { r0[t] += r0[t + off]; r1[t] += r1[t + off]; r2[t] += r2[t + off]; }
        __syncthreads();
    }
    __shared__ float w0s, w1s;
    if (t == 0) {
        w0s = r0[0] + pwb[o * 2 + 0];
        w1s = r1[0] + pwb[o * 2 + 1];
        g_gbias[br][b * Cn + o] = r2[0] + bb[o];
    }
    __syncthreads();
    if (t < 18) {
        int j = t / 9, k = t % 9;
        int g = o >> 1;
        float w = w0s * g_wsp[br][(size_t)(b * 256 + (g * 2 + 0) * 2 + j) * 9 + k]
                + w1s * g_wsp[br][(size_t)(b * 256 + (g * 2 + 1) * 2 + j) * 9 + k];
        g_weff[br][(size_t)((b * Cn + o) * 2 + j) * 9 + k] = w;
    }
}

// ---------------------------------------------------------------------------
__global__ void k_istats(const float* __restrict__ x, int H, int br) {
    int bc = blockIdx.x;
    int HW = H * H;
    const float4* p4 = (const float4*)(x + (size_t)bc * HW);
    int n4 = HW >> 2;
    float s = 0.f, ss = 0.f;
    for (int i = threadIdx.x; i < n4; i += 256) {
        float4 v = p4[i];
        s += v.x + v.y + v.z + v.w;
        ss += v.x * v.x + v.y * v.y + v.z * v.z + v.w * v.w;
    }
    __shared__ float rs[256], rss[256];
    rs[threadIdx.x] = s; rss[threadIdx.x] = ss;
    __syncthreads();
    for (int off = 128; off; off >>= 1) {
        if (threadIdx.x < off) { rs[threadIdx.x] += rs[threadIdx.x + off]; rss[threadIdx.x] += rss[threadIdx.x + off]; }
        __syncthreads();
    }
    if (threadIdx.x == 0) {
        float m = rs[0] / HW;
        float var = rss[0] / HW - m * m;
        g_m1[br][bc] = m;
        g_rs1[br][bc] = rsqrtf(var + EPSF);
    }
}

// ---------------------------------------------------------------------------
// Fused grouped conv (inorm1 inline), reflect pad, writes padded half2
// interior AND the reflect halo (boundary tiles own all reflected cells).
// ---------------------------------------------------------------------------
__global__ void k_gconv(const float* __restrict__ xin, int H, int W2p, size_t off2, int br) {
    int bg = blockIdx.y;
    int b = bg >> 6, g = bg & 63;
    int tiles = H >> 5;
    int ty0 = (blockIdx.x / tiles) << 5;
    int tx0 = (blockIdx.x % tiles) << 5;
    int t = threadIdx.x;

    __shared__ float tile[2][34][34];
    __shared__ float w[2][2][9];
    __shared__ float bsh[2];

    if (t < 36) {
        int oc = t / 18, j = (t / 9) & 1, k = t % 9;
        w[oc][j][k] = g_weff[br][(size_t)((b * Cn + g * 2 + oc) * 2 + j) * 9 + k];
    }
    if (t < 2) bsh[t] = g_gbias[br][b * Cn + g * 2 + t];

#pragma unroll
    for (int ic = 0; ic < 2; ic++) {
        int ch = g * 2 + ic;
        float m = g_m1[br][b * Cn + ch], rs = g_rs1[br][b * Cn + ch];
        const float* xp = xin + (size_t)(b * Cn + ch) * H * H;
        for (int i = t; i < 34 * 34; i += 256) {
            int ly = i / 34, lx = i % 34;
            int gy = ty0 - 1 + ly, gx = tx0 - 1 + lx;
            gy = gy < 0 ? -gy : (gy >= H ? 2 * H - 2 - gy : gy);
            gx = gx < 0 ? -gx : (gx >= H ? 2 * H - 2 - gx : gx);
            tile[ic][ly][lx] = (xp[(size_t)gy * H + gx] - m) * rs;
        }
    }
    __syncthreads();

    __half2* dst = g_y2p + off2 + (size_t)(b * 64 + g) * (H + 2) * W2p;
    for (int p = t; p < 1024; p += 256) {
        int y = p >> 5, x = p & 31;
        float a0 = bsh[0], a1 = bsh[1];
#pragma unroll
        for (int ic = 0; ic < 2; ic++)
#pragma unroll
            for (int ky = 0; ky < 3; ky++)
#pragma unroll
                for (int kx = 0; kx < 3; kx++) {
                    float v = tile[ic][y + ky][x + kx];
                    a0 += v * w[0][ic][ky * 3 + kx];
                    a1 += v * w[1][ic][ky * 3 + kx];
                }
        __half2 h2 = __floats2half2_rn(a0, a1);
        int gy = ty0 + y, gx = tx0 + x;
        size_t rowi = (size_t)(1 + gy) * W2p;
        dst[rowi + 1 + gx] = h2;
        // reflect halo (padded row0 = orig row1, col0 = orig col1, etc.)
        if (gx == 1)     dst[rowi] = h2;
        if (gx == H - 2) dst[rowi + H + 1] = h2;
        if (gy == 1) {
            dst[1 + gx] = h2;
            if (gx == 1)     dst[0] = h2;
            if (gx == H - 2) dst[H + 1] = h2;
        }
        if (gy == H - 2) {
            size_t rb = (size_t)(H + 1) * W2p;
            dst[rb + 1 + gx] = h2;
            if (gx == 1)     dst[rb] = h2;
            if (gx == H - 2) dst[rb + H + 1] = h2;
        }
    }
}

// ===========================================================================
// Dense 3x3 conv via mma.sync m16n8k16 fp16 (tap-loop implicit GEMM).
// A fragments loaded as one LDS.128 per m-tile per tap (fragment-major smem).
// ===========================================================================
#define AW_BYTES 36864
#define IT_BYTES 6912
#define SMEM_MMA (2 * AW_BYTES + 2 * IT_BYTES)   // 87552

__device__ __forceinline__ uint32_t s2u(const void* p) {
    uint32_t a;
    asm("{ .reg .u64 t; cvta.to.shared.u64 t, %1; cvt.u32.u64 %0, t; }" : "=r"(a) : "l"(p));
    return a;
}

#define MMAH(d, a0, a1, a2, a3, b0, b1)                                  \
    asm volatile("mma.sync.aligned.m16n8k16.row.col.f32.f16.f16.f32 "    \
                 "{%0,%1,%2,%3}, {%4,%5,%6,%7}, {%8,%9}, {%0,%1,%2,%3};" \
                 : "+f"(d[0]), "+f"(d[1]), "+f"(d[2]), "+f"(d[3])        \
                 : "r"(a0), "r"(a1), "r"(a2), "r"(a3),                   \
                   "r"(b0), "r"(b1))

__global__ void __launch_bounds__(256) k_dconv_mma(
    const float* __restrict__ cb, const __half2* __restrict__ wT,
    int H, int W2p, size_t inoff2, size_t coutoff2, int statoff) {

    extern __shared__ __align__(16) char smem[];
    const int t = threadIdx.x;
    const int wid = t >> 5, lane = t & 31;
    const int gid = lane >> 2, tig = lane & 3;
    const int moff = (wid & 3) * 32, noff = (wid >> 2) * 64;
    const int mt0 = (wid & 3) * 2;
    const int px0 = blockIdx.x * 32, py0 = blockIdx.y * 4;
    const int b = blockIdx.z;
    const int HW = H * H;
    uint32_t sb = s2u(smem);

    const __half2* inb2 = g_y2p + inoff2 + (size_t)b * 64 * (H + 2) * W2p;

    int bidx[8];
#pragma unroll
    for (int j = 0; j < 8; j++) {
        int n = noff + j * 8 + gid;
        bidx[j] = (n >> 5) * 36 + (n & 31);
    }

    float acc[2][8][4];
#pragma unroll
    for (int m = 0; m < 2; m++)
#pragma unroll
        for (int j = 0; j < 8; j++)
#pragma unroll
            for (int q = 0; q < 4; q++) acc[m][j][q] = 0.f;

    auto issue = [&](int cc) {
        int s = cc & 1;
        const __half2* srcw = wT + (size_t)cc * 9216;
        uint32_t dstw = sb + s * AW_BYTES;
        for (int u = t; u < 2304; u += 256)
            asm volatile("cp.async.cg.shared.global [%0], [%1], 16;" ::
                         "r"(dstw + u * 16), "l"(srcw + u * 4));
        uint32_t dsti = sb + 2 * AW_BYTES + s * IT_BYTES;
        for (int v = t; v < 432; v += 256) {
            int kp = v / 54, rem = v % 54;
            int ry = rem / 9, q = rem % 9;
            const __half2* g = inb2 +
                ((size_t)(cc * 8 + kp) * (H + 2) + (py0 + ry)) * W2p + px0 + q * 4;
            asm volatile("cp.async.cg.shared.global [%0], [%1], 16;" ::
                         "r"(dsti + (uint32_t)((kp * 216 + ry * 36 + q * 4) * 4)), "l"(g));
        }
        asm volatile("cp.async.commit_group;" ::: "memory");
    };

    issue(0);
    for (int cc = 0; cc < 8; cc++) {
        asm volatile("cp.async.wait_group 0;" ::: "memory");
        __syncthreads();
        if (cc < 7) issue(cc + 1);

        const uint32_t* Aw = (const uint32_t*)(smem + (cc & 1) * AW_BYTES);
        const uint32_t* IT = (const uint32_t*)(smem + 2 * AW_BYTES + (cc & 1) * IT_BYTES);

#pragma unroll
        for (int tap = 0; tap < 9; tap++) {
            uint4 av[2];
            av[0] = *reinterpret_cast<const uint4*>(Aw + tap * 1024 + (mt0 + 0) * 128 + lane * 4);
            av[1] = *reinterpret_cast<const uint4*>(Aw + tap * 1024 + (mt0 + 1) * 128 + lane * 4);
            int toff = tig * 216 + (tap / 3) * 36 + (tap % 3);
#pragma unroll
            for (int j = 0; j < 8; j++) {
                uint32_t b0 = IT[toff + bidx[j]];
                uint32_t b1 = IT[toff + 864 + bidx[j]];
                MMAH(acc[0][j], av[0].x, av[0].y, av[0].z, av[0].w, b0, b1);
                MMAH(acc[1][j], av[1].x, av[1].y, av[1].z, av[1].w, b0, b1);
            }
        }
    }

    // ---- epilogue: bias + half2 store to scratch + stats ----
#pragma unroll
    for (int m = 0; m < 2; m++) {
        int ocm = moff + m * 16 + gid;
        float bv0 = cb[ocm], bv1 = cb[ocm + 8];
        float s0 = 0.f, q0 = 0.f, s1 = 0.f, q1 = 0.f;
        __half2* o0 = g_cout + coutoff2 + (((size_t)(b * Cn + ocm) * HW) >> 1);
        __half2* o1 = g_cout + coutoff2 + (((size_t)(b * Cn + ocm + 8) * HW) >> 1);
#pragma unroll
        for (int j = 0; j < 8; j++) {
            int n = noff + j * 8 + tig * 2;
            int pr = py0 + (n >> 5), pc = px0 + (n & 31);
            float v00 = acc[m][j][0] + bv0, v01 = acc[m][j][1] + bv0;
            float v10 = acc[m][j][2] + bv1, v11 = acc[m][j][3] + bv1;
            size_t pp = ((size_t)pr * H + pc) >> 1;
            o0[pp] = __floats2half2_rn(v00, v01);
            o1[pp] = __floats2half2_rn(v10, v11);
            s0 += v00 + v01; q0 += v00 * v00 + v01 * v01;
            s1 += v10 + v11; q1 += v10 * v10 + v11 * v11;
        }
#pragma unroll
        for (int o = 1; o <= 2; o <<= 1) {
            s0 += __shfl_xor_sync(0xffffffffu, s0, o);
            q0 += __shfl_xor_sync(0xffffffffu, q0, o);
            s1 += __shfl_xor_sync(0xffffffffu, s1, o);
            q1 += __shfl_xor_sync(0xffffffffu, q1, o);
        }
        if (tig == 0) {
            atomicAdd(&g_sum[statoff + b * Cn + ocm], s0);
            atomicAdd(&g_ssq[statoff + b * Cn + ocm], q0);
            atomicAdd(&g_sum[statoff + b * Cn + ocm + 8], s1);
            atomicAdd(&g_ssq[statoff + b * Cn + ocm + 8], q1);
        }
    }
}

// ---------------------------------------------------------------------------
// Final: read half2 conv scratch, instance norm + leaky ReLU, write fp32 out.
// ---------------------------------------------------------------------------
__global__ void k_final(float* __restrict__ out) {
    size_t totalp = (HFTOT + LFTOT) >> 1;
    for (size_t idx = (size_t)blockIdx.x * blockDim.x + threadIdx.x; idx < totalp;
         idx += (size_t)gridDim.x * blockDim.x) {
        size_t e = idx << 1;
        int stat; float inv;
        if (e < HFTOT) {
            stat = (int)(e >> 16);
            inv = 1.f / 65536.f;
        } else {
            stat = Bn * Cn + (int)((e - HFTOT) >> 14);
            inv = 1.f / 16384.f;
        }
        float m = g_sum[stat] * inv;
        float var = g_ssq[stat] * inv - m * m;
        float rs = rsqrtf(var + EPSF);
        float2 v = __half22float2(g_cout[idx]);
        float a = (v.x - m) * rs;
        float c = (v.y - m) * rs;
        a = a >= 0.f ? a : 0.2f * a;
        c = c >= 0.f ? c : 0.2f * c;
        reinterpret_cast<float2*>(out)[idx] = make_float2(a, c);
    }
}

// ---------------------------------------------------------------------------
extern "C" void kernel_launch(void* const* d_in, const int* in_sizes, int n_in,
                              void* d_out, int out_size) {
    const float* c_hf = (const float*)d_in[0];
    const float* c_lf = (const float*)d_in[1];
    const float* s_hf = (const float*)d_in[2];
    const float* s_lf = (const float*)d_in[3];
    const float* kp_h_sp_w = (const float*)d_in[4];
    const float* kp_h_sp_b = (const float*)d_in[5];
    const float* kp_h_pw_w = (const float*)d_in[6];
    const float* kp_h_pw_b = (const float*)d_in[7];
    const float* kp_h_b_w  = (const float*)d_in[8];
    const float* kp_h_b_b  = (const float*)d_in[9];
    const float* kp_l_sp_w = (const float*)d_in[10];
    const float* kp_l_sp_b = (const float*)d_in[11];
    const float* kp_l_pw_w = (const float*)d_in[12];
    const float* kp_l_pw_b = (const float*)d_in[13];
    const float* kp_l_b_w  = (const float*)d_in[14];
    const float* kp_l_b_b  = (const float*)d_in[15];
    const float* conv_h_w  = (const float*)d_in[16];
    const float* conv_h_b  = (const float*)d_in[17];
    const float* conv_l_w  = (const float*)d_in[18];
    const float* conv_l_b  = (const float*)d_in[19];
    float* out = (float*)d_out;

    cudaFuncSetAttribute(k_dconv_mma, cudaFuncAttributeMaxDynamicSharedMemorySize, SMEM_MMA);

    __half2* wTh; cudaGetSymbolAddress((void**)&wTh, g_wTh);
    __half2* wTl = wTh + WTSZ;

    // Fork two side streams for the independent hf/lf branches.
    cudaStream_t s1, s2;
    cudaStreamCreateWithFlags(&s1, cudaStreamNonBlocking);
    cudaStreamCreateWithFlags(&s2, cudaStreamNonBlocking);
    cudaEvent_t e0, e1, e2;
    cudaEventCreateWithFlags(&e0, cudaEventDisableTiming);
    cudaEventCreateWithFlags(&e1, cudaEventDisableTiming);
    cudaEventCreateWithFlags(&e2, cudaEventDisableTiming);

    k_prep<<<(2 * Cn * 64 * 9 + 255) / 256, 256>>>(conv_h_w, conv_l_w);
    cudaEventRecord(e0, 0);
    cudaStreamWaitEvent(s1, e0, 0);
    cudaStreamWaitEvent(s2, e0, 0);

    // ---- HF branch on s1 ----
    k_wsp<<<Bn * 256, 128, 0, s1>>>(s_hf, kp_h_sp_w, kp_h_sp_b, 0);
    k_weff<<<Bn * Cn, 128, 0, s1>>>(s_hf, kp_h_pw_w, kp_h_pw_b, kp_h_b_w, kp_h_b_b, 0);
    k_istats<<<Bn * Cn, 256, 0, s1>>>(c_hf, Hh, 0);
    k_gconv<<<dim3(64, Bn * Gn), 256, 0, s1>>>(c_hf, Hh, W2H, 0, 0);
    k_dconv_mma<<<dim3(Hh / 32, Hh / 4, Bn), 256, SMEM_MMA, s1>>>(
        conv_h_b, wTh, Hh, W2H, 0, 0, 0);

    // ---- LF branch on s2 ----
    k_wsp<<<Bn * 256, 128, 0, s2>>>(s_lf, kp_l_sp_w, kp_l_sp_b, 1);
    k_weff<<<Bn * Cn, 128, 0, s2>>>(s_lf, kp_l_pw_w, kp_l_pw_b, kp_l_b_w, kp_l_b_b, 1);
    k_istats<<<Bn * Cn, 256, 0, s2>>>(c_lf, Hl, 1);
    k_gconv<<<dim3(16, Bn * Gn), 256, 0, s2>>>(c_lf, Hl, W2L, HFP2, 1);
    k_dconv_mma<<<dim3(Hl / 32, Hl / 4, Bn), 256, SMEM_MMA, s2>>>(
        conv_l_b, wTl, Hl, W2L, HFP2, HFTOT / 2, Bn * Cn);

    // ---- join, then final norm + lrelu on the main stream ----
    cudaEventRecord(e1, s1);
    cudaEventRecord(e2, s2);
    cudaStreamWaitEvent(0, e1, 0);
    cudaStreamWaitEvent(0, e2, 0);
    k_final<<<16384, 256>>>(out);

    cudaEventDestroy(e0);
    cudaEventDestroy(e1);
    cudaEventDestroy(e2);
    cudaStreamDestroy(s1);
    cudaStreamDestroy(s2);
}